// round 2
// baseline (speedup 1.0000x reference)
#include <cuda_runtime.h>
#include <math.h>

#define WIDTH 128
#define NMAX  50176   // nodes (50000 actual, padded)

// ---- scratch (device globals: no allocation allowed) ----
__device__ float g_xx[NMAX * WIDTH];
__device__ float g_Q [NMAX * WIDTH];
__device__ float g_K [NMAX * WIDTH];
__device__ float g_V [NMAX * WIDTH];
__device__ float g_X2[NMAX * WIDTH];
__device__ float g_T  [3 * 34 * WIDTH];   // per-vocab remix tables
__device__ float g_T81[3 * 81 * WIDTH];   // combined 81-combo tables

__device__ __forceinline__ float gelu1(float x) {
    return 0.5f * x * (1.0f + erff(x * 0.7071067811865475f));
}

__device__ __forceinline__ unsigned long long fma2(unsigned long long a,
                                                   unsigned long long b,
                                                   unsigned long long c) {
    unsigned long long d;
    asm("fma.rn.f32x2 %0, %1, %2, %3;" : "=l"(d) : "l"(a), "l"(b), "l"(c));
    return d;
}
__device__ __forceinline__ float2 unpk(unsigned long long v) {
    float2 r;
    asm("mov.b64 {%0, %1}, %2;" : "=f"(r.x), "=f"(r.y) : "l"(v));
    return r;
}

// ============================================================================
// Tables: T[j][row][o] = xw_c * scale * (emb_c[row] @ remix_j_w)[o]
// ============================================================================
__global__ void k_tables(const float* __restrict__ r0w, const float* __restrict__ r1w,
                         const float* __restrict__ r2w,
                         const float* __restrict__ e0, const float* __restrict__ e1,
                         const float* __restrict__ e2, const float* __restrict__ e3,
                         const float* __restrict__ einit, const float* __restrict__ init0)
{
    int j = blockIdx.x;        // 0..2
    int r = blockIdx.y;        // 0..33
    int o = threadIdx.x;       // 0..127
    int c, lr;
    if (r < 6)       { c = 0; lr = r; }
    else if (r < 13) { c = 1; lr = r - 6; }
    else if (r < 16) { c = 2; lr = r - 13; }
    else             { c = 3; lr = r - 16; }
    const float* emb = (c == 0) ? e0 : (c == 1) ? e1 : (c == 2) ? e2 : e3;
    const float* rw  = (j == 0) ? r0w : (j == 1) ? r1w : r2w;

    __shared__ float er[64];
    if (o < 64) er[o] = emb[lr * 64 + o];
    __syncthreads();

    float s = 0.0f;
#pragma unroll
    for (int m = 0; m < 64; m++) s += er[m] * rw[m * WIDTH + o];

    float es = expf(einit[0]) + expf(einit[1]) + expf(einit[2]) + expf(einit[3]);
    float xw = expf(einit[c]) * rsqrtf(es);
    float sf = expf((j == 2) ? init0[3] : init0[2]);
    g_T[(j * 34 + r) * WIDTH + o] = s * xw * sf;
}

// Combined table over the 81 attr combos (attr values in {0,1,2})
__global__ void k_combine()
{
    int j = blockIdx.x, i = blockIdx.y, o = threadIdx.x;
    int d0 = i % 3, d1 = (i / 3) % 3, d2 = (i / 9) % 3, d3 = i / 27;
    g_T81[(j * 81 + i) * WIDTH + o] =
        g_T[(j * 34 + d0) * WIDTH + o] + g_T[(j * 34 + 6 + d1) * WIDTH + o] +
        g_T[(j * 34 + 13 + d2) * WIDTH + o] + g_T[(j * 34 + 16 + d3) * WIDTH + o];
}

// ============================================================================
// 128x128 GEMM tile body (K=128), 256 threads, 8x8 micro-tile, fma.rn.f32x2.
// acc[i][j] = f32x2 pair for (row r0+ty*8+i, cols tx*8+2j, tx*8+2j+1).
// A stored DUPLICATED in smem ((a,a) pairs) -> a-frag loads are broadcast.
// smem: exactly 48KB -> 2 CTAs/SM.
// ============================================================================
#define BK 16
#define SA 256   // As2 row stride in floats (2*128)
#define SB 128

__device__ __forceinline__ void gemm128(const float* __restrict__ A,
                                        const float* __restrict__ W,
                                        int n, int r0,
                                        unsigned long long acc[8][4])
{
    __shared__ float As2[2][BK][SA];
    __shared__ float Bs [2][BK][SB];
    const int tid = threadIdx.x;
    const int ty = tid >> 4;
    const int tx = tid & 15;

#pragma unroll
    for (int i = 0; i < 8; i++)
#pragma unroll
        for (int j = 0; j < 4; j++) acc[i][j] = 0ULL;

    // stage chunk 0
#pragma unroll
    for (int q = 0; q < 2; q++) {
        int s = q * 256 + tid;
        int r = s >> 2, c4 = (s & 3) << 2;
        float4 v = make_float4(0.f, 0.f, 0.f, 0.f);
        if (r0 + r < n) v = *(const float4*)&A[(r0 + r) * WIDTH + c4];
#pragma unroll
        for (int t = 0; t < 4; t++) {
            float xv = (&v.x)[t];
            *(float2*)&As2[0][c4 + t][2 * r] = make_float2(xv, xv);
        }
        int kk = s >> 5, b4 = (s & 31) << 2;
        *(float4*)&Bs[0][kk][b4] = *(const float4*)&W[kk * WIDTH + b4];
    }
    __syncthreads();

#pragma unroll 2
    for (int c = 0; c < 8; c++) {
        const int buf = c & 1;
        float4 ra[2], rb[2];
        if (c < 7) {
            int k0 = (c + 1) * BK;
#pragma unroll
            for (int q = 0; q < 2; q++) {
                int s = q * 256 + tid;
                int r = s >> 2, c4 = (s & 3) << 2;
                ra[q] = make_float4(0.f, 0.f, 0.f, 0.f);
                if (r0 + r < n) ra[q] = *(const float4*)&A[(r0 + r) * WIDTH + k0 + c4];
                int kk = s >> 5, b4 = (s & 31) << 2;
                rb[q] = *(const float4*)&W[(k0 + kk) * WIDTH + b4];
            }
        }
#pragma unroll
        for (int kk = 0; kk < BK; kk++) {
            unsigned long long av[8], bv[4];
            ulonglong2 t0 = *(const ulonglong2*)&As2[buf][kk][16 * ty + 0];
            ulonglong2 t1 = *(const ulonglong2*)&As2[buf][kk][16 * ty + 4];
            ulonglong2 t2 = *(const ulonglong2*)&As2[buf][kk][16 * ty + 8];
            ulonglong2 t3 = *(const ulonglong2*)&As2[buf][kk][16 * ty + 12];
            av[0] = t0.x; av[1] = t0.y; av[2] = t1.x; av[3] = t1.y;
            av[4] = t2.x; av[5] = t2.y; av[6] = t3.x; av[7] = t3.y;
            ulonglong2 u0 = *(const ulonglong2*)&Bs[buf][kk][8 * tx];
            ulonglong2 u1 = *(const ulonglong2*)&Bs[buf][kk][8 * tx + 4];
            bv[0] = u0.x; bv[1] = u0.y; bv[2] = u1.x; bv[3] = u1.y;
#pragma unroll
            for (int i = 0; i < 8; i++)
#pragma unroll
                for (int j = 0; j < 4; j++)
                    acc[i][j] = fma2(av[i], bv[j], acc[i][j]);
        }
        if (c < 7) {
#pragma unroll
            for (int q = 0; q < 2; q++) {
                int s = q * 256 + tid;
                int r = s >> 2, c4 = (s & 3) << 2;
#pragma unroll
                for (int t = 0; t < 4; t++) {
                    float xv = (&ra[q].x)[t];
                    *(float2*)&As2[buf ^ 1][c4 + t][2 * r] = make_float2(xv, xv);
                }
                int kk = s >> 5, b4 = (s & 31) << 2;
                *(float4*)&Bs[buf ^ 1][kk][b4] = rb[q];
            }
        }
        __syncthreads();
    }
}

// ============================================================================
// pre: xx = LayerNorm(x @ pre_w + pre_b)
// ============================================================================
__global__ void __launch_bounds__(256, 2) k_pre(const float* __restrict__ x,
                                                const float* __restrict__ w,
                                                const float* __restrict__ b, int n)
{
    int r0 = blockIdx.x * 128;
    unsigned long long acc[8][4];
    gemm128(x, w, n, r0, acc);

    int ty = threadIdx.x >> 4, tx = threadIdx.x & 15;
    float bb[8];
    *(float4*)&bb[0] = *(const float4*)&b[tx * 8];
    *(float4*)&bb[4] = *(const float4*)&b[tx * 8 + 4];

#pragma unroll
    for (int i = 0; i < 8; i++) {
        int row = r0 + ty * 8 + i;
        float f[8];
#pragma unroll
        for (int j = 0; j < 4; j++) {
            float2 p = unpk(acc[i][j]);
            f[2 * j]     = p.x + bb[2 * j];
            f[2 * j + 1] = p.y + bb[2 * j + 1];
        }
        float s1 = 0.f, s2 = 0.f;
#pragma unroll
        for (int j = 0; j < 8; j++) { s1 += f[j]; s2 += f[j] * f[j]; }
#pragma unroll
        for (int m = 8; m; m >>= 1) {
            s1 += __shfl_xor_sync(0xffffffffu, s1, m);
            s2 += __shfl_xor_sync(0xffffffffu, s2, m);
        }
        float mean = s1 * (1.0f / 128.0f);
        float var  = s2 * (1.0f / 128.0f) - mean * mean;
        float rstd = rsqrtf(var + 1e-5f);
        if (row < n) {
            float4 o0 = make_float4((f[0] - mean) * rstd, (f[1] - mean) * rstd,
                                    (f[2] - mean) * rstd, (f[3] - mean) * rstd);
            float4 o1 = make_float4((f[4] - mean) * rstd, (f[5] - mean) * rstd,
                                    (f[6] - mean) * rstd, (f[7] - mean) * rstd);
            *(float4*)&g_xx[row * WIDTH + tx * 8]     = o0;
            *(float4*)&g_xx[row * WIDTH + tx * 8 + 4] = o1;
        }
    }
}

// ============================================================================
// QKVM: blockIdx.y selects projection (Q/K/V/X2), biases folded.
// ============================================================================
__global__ void __launch_bounds__(256, 2) k_qkvm(
    const float* __restrict__ msg0_w, const float* __restrict__ msg0_b,
    const float* __restrict__ msg1_w, const float* __restrict__ msg1_b,
    const float* __restrict__ msg2_w, const float* __restrict__ msg2_b,
    const float* __restrict__ msg3_w, const float* __restrict__ msg3_b,
    const float* __restrict__ remix0_b, const float* __restrict__ remix1_b,
    const float* __restrict__ remix2_b, const float* __restrict__ init0, int n)
{
    int cb = blockIdx.y;
    const float* W; const float* b1; const float* b2; float* out;
    float sc = 0.0f; int do_gelu = 0;
    float sc_e = expf(init0[2]);
    float sc_v = expf(init0[3]);
    if (cb == 0)      { W = msg1_w; b1 = msg1_b; b2 = remix0_b; sc = sc_e; out = g_Q; }
    else if (cb == 1) { W = msg2_w; b1 = msg2_b; b2 = remix1_b; sc = sc_e; out = g_K; }
    else if (cb == 2) { W = msg3_w; b1 = msg3_b; b2 = remix2_b; sc = sc_v; out = g_V; }
    else              { W = msg0_w; b1 = msg0_b; b2 = 0;        sc = 0.f;  out = g_X2; do_gelu = 1; }

    int r0 = blockIdx.x * 128;
    unsigned long long acc[8][4];
    gemm128(g_xx, W, n, r0, acc);

    int ty = threadIdx.x >> 4, tx = threadIdx.x & 15;
    float bb[8];
    *(float4*)&bb[0] = *(const float4*)&b1[tx * 8];
    *(float4*)&bb[4] = *(const float4*)&b1[tx * 8 + 4];
    if (b2) {
#pragma unroll
        for (int j = 0; j < 8; j++) bb[j] += sc * b2[tx * 8 + j];
    }
#pragma unroll
    for (int i = 0; i < 8; i++) {
        int row = r0 + ty * 8 + i;
        if (row >= n) continue;
        float f[8];
#pragma unroll
        for (int j = 0; j < 4; j++) {
            float2 p = unpk(acc[i][j]);
            f[2 * j]     = p.x + bb[2 * j];
            f[2 * j + 1] = p.y + bb[2 * j + 1];
        }
        if (do_gelu) {
#pragma unroll
            for (int j = 0; j < 8; j++) f[j] = gelu1(f[j]);
        }
        *(float4*)&out[row * WIDTH + tx * 8]     = *(float4*)&f[0];
        *(float4*)&out[row * WIDTH + tx * 8 + 4] = *(float4*)&f[4];
    }
}

// ============================================================================
// Edge phase: one warp per edge, combined 81-combo tables.
// ============================================================================
__global__ void __launch_bounds__(256) k_edge(const int* __restrict__ ei,
                                              const int* __restrict__ ea,
                                              const float* __restrict__ init0, int e)
{
    int gw = blockIdx.x * 8 + (threadIdx.x >> 5);
    if (gw >= e) return;
    int lane = threadIdx.x & 31;

    int src = __ldg(ei + gw);
    int dst = __ldg(ei + e + gw);
    int4 a = __ldg((const int4*)ea + gw);
    int idx = a.x + 3 * a.y + 9 * a.z + 27 * a.w;

    const float4* T = (const float4*)g_T81;   // [3][81][32] float4
    float4 re0 = __ldg(&T[(0 * 81 + idx) * 32 + lane]);
    float4 re1 = __ldg(&T[(1 * 81 + idx) * 32 + lane]);
    float4 re2 = __ldg(&T[(2 * 81 + idx) * 32 + lane]);

    int c4 = lane << 2;
    float4 qv = __ldg((const float4*)&g_Q[dst * WIDTH + c4]);
    float4 kv = __ldg((const float4*)&g_K[src * WIDTH + c4]);
    float4 vv = __ldg((const float4*)&g_V[src * WIDTH + c4]);
    qv.x += re0.x; qv.y += re0.y; qv.z += re0.z; qv.w += re0.w;
    kv.x += re1.x; kv.y += re1.y; kv.z += re1.z; kv.w += re1.w;
    float g0 = gelu1(vv.x + re2.x);
    float g1 = gelu1(vv.y + re2.y);
    float g2 = gelu1(vv.z + re2.z);
    float g3 = gelu1(vv.w + re2.w);

    float s = qv.x * kv.x + qv.y * kv.y + qv.z * kv.z + qv.w * kv.w;
#pragma unroll
    for (int m = 8; m; m >>= 1) s += __shfl_xor_sync(0xffffffffu, s, m);
    // lanes 0-15: head0 sum, lanes 16-31: head1 sum

    float att = expf(s * 0.125f * init0[0] + init0[1]);
    float m0 = g0 * att, m1 = g1 * att, m2 = g2 * att, m3 = g3 * att;

    float* dptr = &g_X2[dst * WIDTH + c4];
    asm volatile("red.global.add.v4.f32 [%0], {%1,%2,%3,%4};"
                 :: "l"(dptr), "f"(m0), "f"(m1), "f"(m2), "f"(m3) : "memory");
}

// ============================================================================
// post: out = x + (X2 @ post_w + post_b)
// ============================================================================
__global__ void __launch_bounds__(256, 2) k_post(const float* __restrict__ w,
                                                 const float* __restrict__ b,
                                                 const float* __restrict__ x,
                                                 float* __restrict__ out, int n)
{
    int r0 = blockIdx.x * 128;
    unsigned long long acc[8][4];
    gemm128(g_X2, w, n, r0, acc);

    int ty = threadIdx.x >> 4, tx = threadIdx.x & 15;
    float bb[8];
    *(float4*)&bb[0] = *(const float4*)&b[tx * 8];
    *(float4*)&bb[4] = *(const float4*)&b[tx * 8 + 4];

#pragma unroll
    for (int i = 0; i < 8; i++) {
        int row = r0 + ty * 8 + i;
        if (row >= n) continue;
        float f[8];
#pragma unroll
        for (int j = 0; j < 4; j++) {
            float2 p = unpk(acc[i][j]);
            f[2 * j]     = p.x + bb[2 * j];
            f[2 * j + 1] = p.y + bb[2 * j + 1];
        }
        float4 x0 = *(const float4*)&x[row * WIDTH + tx * 8];
        float4 x1 = *(const float4*)&x[row * WIDTH + tx * 8 + 4];
        float4 o0 = make_float4(f[0] + x0.x, f[1] + x0.y, f[2] + x0.z, f[3] + x0.w);
        float4 o1 = make_float4(f[4] + x1.x, f[5] + x1.y, f[6] + x1.z, f[7] + x1.w);
        *(float4*)&out[row * WIDTH + tx * 8]     = o0;
        *(float4*)&out[row * WIDTH + tx * 8 + 4] = o1;
    }
}

extern "C" void kernel_launch(void* const* d_in, const int* in_sizes, int n_in,
                              void* d_out, int out_size)
{
    const float* x        = (const float*)d_in[0];
    const int*   ei       = (const int*)  d_in[1];
    const int*   ea       = (const int*)  d_in[2];
    const float* pre_w    = (const float*)d_in[3];
    const float* pre_b    = (const float*)d_in[4];
    const float* msg0_w   = (const float*)d_in[5];
    const float* msg0_b   = (const float*)d_in[6];
    const float* msg1_w   = (const float*)d_in[7];
    const float* msg1_b   = (const float*)d_in[8];
    const float* msg2_w   = (const float*)d_in[9];
    const float* msg2_b   = (const float*)d_in[10];
    const float* msg3_w   = (const float*)d_in[11];
    const float* msg3_b   = (const float*)d_in[12];
    const float* remix0_w = (const float*)d_in[13];
    const float* remix0_b = (const float*)d_in[14];
    const float* remix1_w = (const float*)d_in[15];
    const float* remix1_b = (const float*)d_in[16];
    const float* remix2_w = (const float*)d_in[17];
    const float* remix2_b = (const float*)d_in[18];
    const float* post_w   = (const float*)d_in[19];
    const float* post_b   = (const float*)d_in[20];
    const float* emb0     = (const float*)d_in[21];
    const float* emb1     = (const float*)d_in[22];
    const float* emb2     = (const float*)d_in[23];
    const float* emb3     = (const float*)d_in[24];
    const float* einit    = (const float*)d_in[25];
    const float* init0    = (const float*)d_in[26];

    int n = in_sizes[0] / WIDTH;
    int e = in_sizes[1] / 2;

    dim3 tg(3, 34);
    k_tables<<<tg, 128>>>(remix0_w, remix1_w, remix2_w, emb0, emb1, emb2, emb3, einit, init0);
    dim3 cg(3, 81);
    k_combine<<<cg, 128>>>();

    int gr = (n + 127) / 128;
    k_pre<<<gr, 256>>>(x, pre_w, pre_b, n);

    dim3 qg(gr, 4);
    k_qkvm<<<qg, 256>>>(msg0_w, msg0_b, msg1_w, msg1_b, msg2_w, msg2_b,
                        msg3_w, msg3_b, remix0_b, remix1_b, remix2_b, init0, n);

    k_edge<<<(e + 7) / 8, 256>>>(ei, ea, init0, e);

    k_post<<<gr, 256>>>(post_w, post_b, x, (float*)d_out, n);
}

// round 4
// speedup vs baseline: 1.4749x; 1.4749x over previous
#include <cuda_runtime.h>
#include <cuda_bf16.h>
#include <math.h>
#include <stdint.h>

#define WIDTH 128
#define NMAX  50176
#define TILEB 32768                       // one 128x128 bf16 tile image
#define DSTRIDE 132                       // staging row stride (floats)
#define DSMEM (4 * TILEB + 128 * DSTRIDE * 4)   // 198656 bytes

// ---- scratch (device globals) ----
__device__ float g_xx[NMAX * WIDTH];
__device__ float g_Q [NMAX * WIDTH];
__device__ float g_K [NMAX * WIDTH];
__device__ float g_V [NMAX * WIDTH];
__device__ float g_X2[NMAX * WIDTH];
__device__ float g_T  [3 * 34 * WIDTH];
__device__ float g_T81[3 * 81 * WIDTH];
__device__ unsigned char g_iW[6][2][TILEB];   // weight images: transposed (n x k), hi/lo

__device__ __forceinline__ float gelu1(float x) {
    return 0.5f * x * (1.0f + erff(x * 0.7071067811865475f));
}

// XOR-swizzled offset for a 128-row x 16-chunk (16B chunks) bf16 tile.
__device__ __forceinline__ int soff(int row, int kc) {
    return row * 256 + ((kc ^ (row & 7)) << 4);
}

__device__ __forceinline__ uint32_t smem_u32(const void* p) {
    uint32_t a;
    asm("{ .reg .u64 t; cvta.to.shared.u64 t, %1; cvt.u32.u64 %0, t; }" : "=r"(a) : "l"(p));
    return a;
}

__device__ __forceinline__ void ldm4(uint32_t* r, uint32_t a) {
    asm volatile("ldmatrix.sync.aligned.m8n8.x4.shared.b16 {%0,%1,%2,%3}, [%4];"
                 : "=r"(r[0]), "=r"(r[1]), "=r"(r[2]), "=r"(r[3]) : "r"(a));
}

__device__ __forceinline__ void mma16816(float* c, const uint32_t* a, uint32_t b0, uint32_t b1) {
    asm volatile(
        "mma.sync.aligned.m16n8k16.row.col.f32.bf16.bf16.f32 "
        "{%0,%1,%2,%3}, {%4,%5,%6,%7}, {%8,%9}, {%0,%1,%2,%3};"
        : "+f"(c[0]), "+f"(c[1]), "+f"(c[2]), "+f"(c[3])
        : "r"(a[0]), "r"(a[1]), "r"(a[2]), "r"(a[3]), "r"(b0), "r"(b1));
}

// ============================================================================
// Tables
// ============================================================================
__global__ void k_tables(const float* __restrict__ r0w, const float* __restrict__ r1w,
                         const float* __restrict__ r2w,
                         const float* __restrict__ e0, const float* __restrict__ e1,
                         const float* __restrict__ e2, const float* __restrict__ e3,
                         const float* __restrict__ einit, const float* __restrict__ init0)
{
    int j = blockIdx.x, r = blockIdx.y, o = threadIdx.x;
    int c, lr;
    if (r < 6)       { c = 0; lr = r; }
    else if (r < 13) { c = 1; lr = r - 6; }
    else if (r < 16) { c = 2; lr = r - 13; }
    else             { c = 3; lr = r - 16; }
    const float* emb = (c == 0) ? e0 : (c == 1) ? e1 : (c == 2) ? e2 : e3;
    const float* rw  = (j == 0) ? r0w : (j == 1) ? r1w : r2w;

    __shared__ float er[64];
    if (o < 64) er[o] = emb[lr * 64 + o];
    __syncthreads();

    float s = 0.0f;
#pragma unroll
    for (int m = 0; m < 64; m++) s += er[m] * rw[m * WIDTH + o];

    float es = expf(einit[0]) + expf(einit[1]) + expf(einit[2]) + expf(einit[3]);
    float xw = expf(einit[c]) * rsqrtf(es);
    float sf = expf((j == 2) ? init0[3] : init0[2]);
    g_T[(j * 34 + r) * WIDTH + o] = s * xw * sf;
}

__global__ void k_combine()
{
    int j = blockIdx.x, i = blockIdx.y, o = threadIdx.x;
    int d0 = i % 3, d1 = (i / 3) % 3, d2 = (i / 9) % 3, d3 = i / 27;
    g_T81[(j * 81 + i) * WIDTH + o] =
        g_T[(j * 34 + d0) * WIDTH + o] + g_T[(j * 34 + 6 + d1) * WIDTH + o] +
        g_T[(j * 34 + 13 + d2) * WIDTH + o] + g_T[(j * 34 + 16 + d3) * WIDTH + o];
}

// ============================================================================
// Weight prep: Bt[n][k] = W[k][n], bf16 hi/lo, swizzled image.
// 48 blocks = 6 weights x 8 row-slices of 16 n-rows.
// ============================================================================
__global__ void __launch_bounds__(256) k_prepw(const float* __restrict__ w0,
    const float* __restrict__ w1, const float* __restrict__ w2,
    const float* __restrict__ w3, const float* __restrict__ w4,
    const float* __restrict__ w5)
{
    int wi = blockIdx.x >> 3, sl = blockIdx.x & 7;
    const float* W = (wi == 0) ? w0 : (wi == 1) ? w1 : (wi == 2) ? w2
                   : (wi == 3) ? w3 : (wi == 4) ? w4 : w5;
    int nrow = sl * 16 + (threadIdx.x >> 4);
    int kc = threadIdx.x & 15;
    __nv_bfloat16 h8[8], l8[8];
#pragma unroll
    for (int j = 0; j < 8; j++) {
        float v = W[(kc * 8 + j) * WIDTH + nrow];   // transpose read
        h8[j] = __float2bfloat16(v);
        l8[j] = __float2bfloat16(v - __bfloat162float(h8[j]));
    }
    int off = soff(nrow, kc);
    *(uint4*)(g_iW[wi][0] + off) = *(uint4*)h8;
    *(uint4*)(g_iW[wi][1] + off) = *(uint4*)l8;
}

// ============================================================================
// mma.sync GEMM: 128x128 tile, K=128, fp32-accurate via bf16 hi/lo (3 passes).
// mode 0 = PRE (bias+LN -> g_xx), 1 = QKVM (4 weights), 2 = POST (residual -> dout)
// ============================================================================
__global__ void __launch_bounds__(256, 1)
k_mma(int mode, const float* __restrict__ x,
      const float* __restrict__ bias0,
      const float* __restrict__ m0b, const float* __restrict__ m1b,
      const float* __restrict__ m2b, const float* __restrict__ m3b,
      const float* __restrict__ r0b, const float* __restrict__ r1b,
      const float* __restrict__ r2b,
      const float* __restrict__ init0, float* __restrict__ dout, int n)
{
    extern __shared__ unsigned char sm[];
    const uint32_t sbase = smem_u32(sm);
    const uint32_t sAh = sbase, sAl = sbase + TILEB;
    const uint32_t sBh = sbase + 2 * TILEB, sBl = sbase + 3 * TILEB;
    float* Dst = (float*)(sm + 4 * TILEB);

    const int tid = threadIdx.x;
    const int wid = tid >> 5, lane = tid & 31;
    const int wr = wid >> 1, wc = wid & 1;
    const int tile = blockIdx.x, r0 = tile * 128;

    // ---- A tile: fp32 -> bf16 hi/lo, swizzled smem ----
    const float* Asrc = (mode == 0) ? x : (mode == 1) ? g_xx : g_X2;
#pragma unroll
    for (int it = 0; it < 8; it++) {
        int c = tid + it * 256;
        int row = c >> 4, kc = c & 15;
        int gr = r0 + row;
        float v[8];
        if (gr < n) {
            float4 a = *(const float4*)&Asrc[gr * WIDTH + kc * 8];
            float4 b = *(const float4*)&Asrc[gr * WIDTH + kc * 8 + 4];
            v[0] = a.x; v[1] = a.y; v[2] = a.z; v[3] = a.w;
            v[4] = b.x; v[5] = b.y; v[6] = b.z; v[7] = b.w;
        } else {
#pragma unroll
            for (int j = 0; j < 8; j++) v[j] = 0.0f;
        }
        __nv_bfloat16 h8[8], l8[8];
#pragma unroll
        for (int j = 0; j < 8; j++) {
            h8[j] = __float2bfloat16(v[j]);
            l8[j] = __float2bfloat16(v[j] - __bfloat162float(h8[j]));
        }
        int off = soff(row, kc);
        *(uint4*)(sm + (sAh - sbase) + off) = *(uint4*)h8;
        *(uint4*)(sm + (sAl - sbase) + off) = *(uint4*)l8;
    }

    const int nw = (mode == 1) ? 4 : 1;
    for (int iw = 0; iw < nw; iw++) {
        int widx = (mode == 0) ? 0 : (mode == 2) ? 5 : (iw + 1);
        // copy weight images into smem
        {
            const uint4* sh = (const uint4*)g_iW[widx][0];
            const uint4* sl = (const uint4*)g_iW[widx][1];
            uint4* dh = (uint4*)(sm + 2 * TILEB);
            uint4* dl = (uint4*)(sm + 3 * TILEB);
#pragma unroll
            for (int i = 0; i < 8; i++) { dh[tid + i * 256] = sh[tid + i * 256];
                                          dl[tid + i * 256] = sl[tid + i * 256]; }
        }
        __syncthreads();

        float acc[2][8][4];
#pragma unroll
        for (int i = 0; i < 2; i++)
#pragma unroll
            for (int j = 0; j < 8; j++)
#pragma unroll
                for (int q = 0; q < 4; q++) acc[i][j][q] = 0.0f;

#pragma unroll
        for (int pass = 0; pass < 3; pass++) {
            uint32_t Ab = (pass == 2) ? sAl : sAh;
            uint32_t Bb = (pass == 1) ? sBl : sBh;
#pragma unroll
            for (int kk = 0; kk < 8; kk++) {
                uint32_t a[2][4], b[4][4];
#pragma unroll
                for (int mt = 0; mt < 2; mt++) {
                    int row = wr * 32 + mt * 16 + (lane & 15);
                    int kc = 2 * kk + (lane >> 4);
                    ldm4(a[mt], Ab + soff(row, kc));
                }
#pragma unroll
                for (int nt = 0; nt < 4; nt++) {
                    int nn = wc * 64 + nt * 16 + (lane & 7) + ((lane >> 4) << 3);
                    int kc = 2 * kk + ((lane >> 3) & 1);
                    ldm4(b[nt], Bb + soff(nn, kc));
                }
#pragma unroll
                for (int mt = 0; mt < 2; mt++)
#pragma unroll
                    for (int nt = 0; nt < 4; nt++) {
                        mma16816(acc[mt][2 * nt],     a[mt], b[nt][0], b[nt][1]);
                        mma16816(acc[mt][2 * nt + 1], a[mt], b[nt][2], b[nt][3]);
                    }
            }
        }
        __syncthreads();

        // ---- stage D fragments to padded smem ----
#pragma unroll
        for (int mt = 0; mt < 2; mt++)
#pragma unroll
            for (int j = 0; j < 8; j++) {
                int row = wr * 32 + mt * 16 + (lane >> 2);
                int col = wc * 64 + j * 8 + 2 * (lane & 3);
                Dst[row * DSTRIDE + col]           = acc[mt][j][0];
                Dst[row * DSTRIDE + col + 1]       = acc[mt][j][1];
                Dst[(row + 8) * DSTRIDE + col]     = acc[mt][j][2];
                Dst[(row + 8) * DSTRIDE + col + 1] = acc[mt][j][3];
            }
        __syncthreads();

        // ---- copy-out (fused epilogue), warp w handles rows 16w..16w+15 ----
        if (mode == 0) {
            float4 bb = __ldg((const float4*)&bias0[lane * 4]);
#pragma unroll
            for (int r = 0; r < 16; r++) {
                int row = wid * 16 + r;
                int gr = r0 + row;
                float4 v = *(float4*)&Dst[row * DSTRIDE + lane * 4];
                v.x += bb.x; v.y += bb.y; v.z += bb.z; v.w += bb.w;
                float s1 = v.x + v.y + v.z + v.w;
                float s2 = v.x * v.x + v.y * v.y + v.z * v.z + v.w * v.w;
#pragma unroll
                for (int m = 16; m; m >>= 1) {
                    s1 += __shfl_xor_sync(0xffffffffu, s1, m);
                    s2 += __shfl_xor_sync(0xffffffffu, s2, m);
                }
                float mean = s1 * (1.0f / 128.0f);
                float var  = s2 * (1.0f / 128.0f) - mean * mean;
                float rstd = rsqrtf(var + 1e-5f);
                if (gr < n) {
                    float4 o = make_float4((v.x - mean) * rstd, (v.y - mean) * rstd,
                                           (v.z - mean) * rstd, (v.w - mean) * rstd);
                    *(float4*)&g_xx[gr * WIDTH + lane * 4] = o;
                }
            }
        } else if (mode == 1) {
            const float* b1; const float* b2; float* out; float sc; int dg = 0;
            float sc_e = expf(init0[2]);
            float sc_v = expf(init0[3]);
            if (iw == 0)      { b1 = m1b; b2 = r0b; sc = sc_e; out = g_Q; }
            else if (iw == 1) { b1 = m2b; b2 = r1b; sc = sc_e; out = g_K; }
            else if (iw == 2) { b1 = m3b; b2 = r2b; sc = sc_v; out = g_V; }
            else              { b1 = m0b; b2 = 0;   sc = 0.f;  out = g_X2; dg = 1; }
            float4 bb = __ldg((const float4*)&b1[lane * 4]);
            if (b2) {
                float4 b2v = __ldg((const float4*)&b2[lane * 4]);
                bb.x += sc * b2v.x; bb.y += sc * b2v.y;
                bb.z += sc * b2v.z; bb.w += sc * b2v.w;
            }
#pragma unroll
            for (int r = 0; r < 16; r++) {
                int row = wid * 16 + r;
                int gr = r0 + row;
                if (gr >= n) continue;
                float4 v = *(float4*)&Dst[row * DSTRIDE + lane * 4];
                v.x += bb.x; v.y += bb.y; v.z += bb.z; v.w += bb.w;
                if (dg) { v.x = gelu1(v.x); v.y = gelu1(v.y);
                          v.z = gelu1(v.z); v.w = gelu1(v.w); }
                *(float4*)&out[gr * WIDTH + lane * 4] = v;
            }
        } else {
            float4 bb = __ldg((const float4*)&bias0[lane * 4]);
#pragma unroll
            for (int r = 0; r < 16; r++) {
                int row = wid * 16 + r;
                int gr = r0 + row;
                if (gr >= n) continue;
                float4 v = *(float4*)&Dst[row * DSTRIDE + lane * 4];
                float4 xv = __ldg((const float4*)&x[gr * WIDTH + lane * 4]);
                float4 o = make_float4(v.x + bb.x + xv.x, v.y + bb.y + xv.y,
                                       v.z + bb.z + xv.z, v.w + bb.w + xv.w);
                *(float4*)&dout[gr * WIDTH + lane * 4] = o;
            }
        }
        __syncthreads();
    }
}

// ============================================================================
// Edge phase: one warp per edge, T81 combined tables, red.v4 aggregation.
// ============================================================================
__global__ void __launch_bounds__(256) k_edge(const int* __restrict__ ei,
                                              const int* __restrict__ ea,
                                              const float* __restrict__ init0, int e)
{
    int gw = blockIdx.x * 8 + (threadIdx.x >> 5);
    if (gw >= e) return;
    int lane = threadIdx.x & 31;

    int src = __ldg(ei + gw);
    int dst = __ldg(ei + e + gw);
    int4 a = __ldg((const int4*)ea + gw);
    int idx = a.x + 3 * a.y + 9 * a.z + 27 * a.w;

    const float4* T = (const float4*)g_T81;
    float4 re0 = __ldg(&T[(0 * 81 + idx) * 32 + lane]);
    float4 re1 = __ldg(&T[(1 * 81 + idx) * 32 + lane]);
    float4 re2 = __ldg(&T[(2 * 81 + idx) * 32 + lane]);

    int c4 = lane << 2;
    float4 qv = __ldg((const float4*)&g_Q[dst * WIDTH + c4]);
    float4 kv = __ldg((const float4*)&g_K[src * WIDTH + c4]);
    float4 vv = __ldg((const float4*)&g_V[src * WIDTH + c4]);
    qv.x += re0.x; qv.y += re0.y; qv.z += re0.z; qv.w += re0.w;
    kv.x += re1.x; kv.y += re1.y; kv.z += re1.z; kv.w += re1.w;
    float g0 = gelu1(vv.x + re2.x);
    float g1 = gelu1(vv.y + re2.y);
    float g2 = gelu1(vv.z + re2.z);
    float g3 = gelu1(vv.w + re2.w);

    float s = qv.x * kv.x + qv.y * kv.y + qv.z * kv.z + qv.w * kv.w;
#pragma unroll
    for (int m = 8; m; m >>= 1) s += __shfl_xor_sync(0xffffffffu, s, m);

    float att = expf(s * 0.125f * init0[0] + init0[1]);
    float m0 = g0 * att, m1 = g1 * att, m2 = g2 * att, m3 = g3 * att;

    float* dptr = &g_X2[dst * WIDTH + c4];
    asm volatile("red.global.add.v4.f32 [%0], {%1,%2,%3,%4};"
                 :: "l"(dptr), "f"(m0), "f"(m1), "f"(m2), "f"(m3) : "memory");
}

extern "C" void kernel_launch(void* const* d_in, const int* in_sizes, int n_in,
                              void* d_out, int out_size)
{
    const float* x        = (const float*)d_in[0];
    const int*   ei       = (const int*)  d_in[1];
    const int*   ea       = (const int*)  d_in[2];
    const float* pre_w    = (const float*)d_in[3];
    const float* pre_b    = (const float*)d_in[4];
    const float* msg0_w   = (const float*)d_in[5];
    const float* msg0_b   = (const float*)d_in[6];
    const float* msg1_w   = (const float*)d_in[7];
    const float* msg1_b   = (const float*)d_in[8];
    const float* msg2_w   = (const float*)d_in[9];
    const float* msg2_b   = (const float*)d_in[10];
    const float* msg3_w   = (const float*)d_in[11];
    const float* msg3_b   = (const float*)d_in[12];
    const float* remix0_w = (const float*)d_in[13];
    const float* remix0_b = (const float*)d_in[14];
    const float* remix1_w = (const float*)d_in[15];
    const float* remix1_b = (const float*)d_in[16];
    const float* remix2_w = (const float*)d_in[17];
    const float* remix2_b = (const float*)d_in[18];
    const float* post_w   = (const float*)d_in[19];
    const float* post_b   = (const float*)d_in[20];
    const float* emb0     = (const float*)d_in[21];
    const float* emb1     = (const float*)d_in[22];
    const float* emb2     = (const float*)d_in[23];
    const float* emb3     = (const float*)d_in[24];
    const float* einit    = (const float*)d_in[25];
    const float* init0    = (const float*)d_in[26];

    int n = in_sizes[0] / WIDTH;
    int e = in_sizes[1] / 2;
    int nt = (n + 127) / 128;

    static int smem_set = 0;
    if (!smem_set) {
        cudaFuncSetAttribute(k_mma, cudaFuncAttributeMaxDynamicSharedMemorySize, DSMEM);
        smem_set = 1;
    }

    k_prepw<<<48, 256>>>(pre_w, msg1_w, msg2_w, msg3_w, msg0_w, post_w);

    dim3 tg(3, 34);
    k_tables<<<tg, 128>>>(remix0_w, remix1_w, remix2_w, emb0, emb1, emb2, emb3, einit, init0);
    dim3 cg(3, 81);
    k_combine<<<cg, 128>>>();

    // PRE: xx = LN(x @ pre_w + pre_b)
    k_mma<<<nt, 256, DSMEM>>>(0, x, pre_b, msg0_b, msg1_b, msg2_b, msg3_b,
                              remix0_b, remix1_b, remix2_b, init0, (float*)d_out, n);
    // QKVM: Q, K, V, X2 from xx
    k_mma<<<nt, 256, DSMEM>>>(1, x, pre_b, msg0_b, msg1_b, msg2_b, msg3_b,
                              remix0_b, remix1_b, remix2_b, init0, (float*)d_out, n);

    k_edge<<<(e + 7) / 8, 256>>>(ei, ea, init0, e);

    // POST: out = x + X2 @ post_w + post_b
    k_mma<<<nt, 256, DSMEM>>>(2, x, post_b, msg0_b, msg1_b, msg2_b, msg3_b,
                              remix0_b, remix1_b, remix2_b, init0, (float*)d_out, n);
}